// round 13
// baseline (speedup 1.0000x reference)
#include <cuda_runtime.h>
#include <cstdint>

#define NB      96
#define MT      16
#define THREADS 128
#define NCTA    512

typedef unsigned long long ull;

// W2 fragments, fragment-linear: [J(16)][KT(16)][lane(32)] x uint4(a0..a3)
__device__ uint4 WFhi4[16 * 16 * 32];
__device__ uint4 WFlo4[16 * 16 * 32];

// ---- helpers ----
__device__ __forceinline__ ull pack2(float x, float y) {
    ull r; asm("mov.b64 %0, {%1, %2};" : "=l"(r) : "f"(x), "f"(y)); return r;
}
__device__ __forceinline__ void unpack2(ull v, float& x, float& y) {
    asm("mov.b64 {%0, %1}, %2;" : "=f"(x), "=f"(y) : "l"(v));
}
__device__ __forceinline__ void ffma2(ull& d, ull a, ull b) {
    asm("fma.rn.f32x2 %0, %1, %2, %0;" : "+l"(d) : "l"(a), "l"(b));
}
// low 16 bits = bf16(f0), high 16 = bf16(f1)
__device__ __forceinline__ uint32_t hi_pair(float f0, float f1) {
    uint32_t v; asm("cvt.rn.bf16x2.f32 %0, %1, %2;" : "=r"(v) : "f"(f1), "f"(f0)); return v;
}
__device__ __forceinline__ uint32_t lo_pair(float f0, float f1, uint32_t hp) {
    float h0 = __uint_as_float(hp << 16);
    float h1 = __uint_as_float(hp & 0xFFFF0000u);
    return hi_pair(f0 - h0, f1 - h1);
}

// non-volatile: lets the compiler schedule loads across MMAs
#define MMA(D, A, B0, B1)                                                  \
    asm("mma.sync.aligned.m16n8k16.row.col.f32.bf16.bf16.f32 "             \
        "{%0,%1,%2,%3},{%4,%5,%6,%7},{%8,%9},{%0,%1,%2,%3};"               \
        : "+f"((D)[0]), "+f"((D)[1]), "+f"((D)[2]), "+f"((D)[3])           \
        : "r"((A).x), "r"((A).y), "r"((A).z), "r"((A).w),                  \
          "r"(B0), "r"(B1))

// ---- prepass: W2 fp32 -> bf16 hi/lo fragments ----
__global__ void prep_kernel(const float* __restrict__ W2) {
    int j = blockIdx.x;          // 0..255 (output row)
    int kp = threadIdx.x;        // 0..127 (k-pair)
    int k = 2 * kp;
    float2 f = *reinterpret_cast<const float2*>(W2 + (size_t)j * 256 + k);
    uint32_t hv = hi_pair(f.x, f.y);
    uint32_t lv = lo_pair(f.x, f.y, hv);
    int J = j >> 4, r = j & 15, KT = k >> 4, q = k & 15;
    int a = ((r >> 3) & 1) | ((q >> 3) << 1);
    int lane = ((r & 7) << 2) | ((q & 7) >> 1);
    int idx = ((((J * 16 + KT) * 32 + lane) << 2) | a);
    reinterpret_cast<uint32_t*>(WFhi4)[idx] = hv;
    reinterpret_cast<uint32_t*>(WFlo4)[idx] = lv;
}

// ---- smem layout (bytes) ----
#define OFF_BFH  0        // 8192: h1 hi B-fragments [mt2][kt16][lane32][r2] u32
#define OFF_BFL  8192     // 8192
#define OFF_W1J  16384    // 6144: [c][k] f32, k pair-contiguous
#define OFF_B1   22528    // 1024
#define OFF_XP   23552    // 768: ull XP[c*16+m]
#define OFF_RED  24320    // 256: [warp4][m16] f32
#define SMEM_TOT 24576

__global__ __launch_bounds__(THREADS, 4)
void net_kernel(const float* __restrict__ X,      // [8192][96][4]
                const float* __restrict__ TN,     // [8192][96]
                const float* __restrict__ DN,     // [8192][96]
                const float* __restrict__ A0,     // [8192]
                const float* __restrict__ S0,     // [8192]
                const float* __restrict__ LAM,
                const float* __restrict__ BUD,
                const float* __restrict__ W1,     // [256][6]
                const float* __restrict__ B1,     // [256]
                const float* __restrict__ B2,     // [256]
                const float* __restrict__ W3,     // [256]
                const float* __restrict__ B3,     // [1]
                float* __restrict__ OUT)          // [8192][96]
{
    extern __shared__ __align__(16) char smem[];
    uint32_t* BFh = reinterpret_cast<uint32_t*>(smem + OFF_BFH);
    uint32_t* BFl = reinterpret_cast<uint32_t*>(smem + OFF_BFL);
    float*    W1J = reinterpret_cast<float*>(smem + OFF_W1J);
    float*    B1s = reinterpret_cast<float*>(smem + OFF_B1);
    ull*      XP  = reinterpret_cast<ull*>(smem + OFF_XP);
    float*    RED = reinterpret_cast<float*>(smem + OFF_RED);

    const int tid  = threadIdx.x;
    const int w    = tid >> 5;       // 0..3
    const int lane = tid & 31;
    const int g    = lane >> 2;      // row-group within fragment
    const int q4   = lane & 3;       // col-group within fragment
    const int base = blockIdx.x * MT;

    // stage W1 transposed [c][k] and B1
    for (int i = tid; i < 6 * 256; i += THREADS) {
        int c = i >> 8, k = i & 255;
        W1J[c * 256 + k] = W1[k * 6 + c];
    }
    for (int i = tid; i < 256; i += THREADS) B1s[i] = B1[i];

    const float lam = LAM[0], bud = BUD[0];
    const float budH     = __fdiv_rn(bud, 96.0f);
    const float per_step = lam * 2.0f + budH;
    const float b3v = B3[0];

    // per-thread epilogue constants: j = (4w+jj)*16 + g + 8*h
    float b2r[4][2], w3r[4][2];
    #pragma unroll
    for (int jj = 0; jj < 4; jj++)
        #pragma unroll
        for (int h = 0; h < 2; h++) {
            int j = (w * 4 + jj) * 16 + g + 8 * h;
            b2r[jj][h] = B2[j];
            w3r[jj][h] = W3[j];
        }

    // register state (threads 0..15) + initial XP staging
    float act = 0.f, st = 0.f, bgt = per_step, cumc = 0.f, adp = 0.f, Sv = 0.f;
    const float4* xrow = reinterpret_cast<const float4*>(X + (size_t)(base + (tid & 15)) * (NB * 4));
    if (tid < MT) {
        act = A0[base + tid];
        st  = S0[base + tid];
        float4 xv = xrow[0];
        XP[0 * 16 + tid] = pack2(xv.x, xv.x);
        XP[1 * 16 + tid] = pack2(xv.y, xv.y);
        XP[2 * 16 + tid] = pack2(xv.z, xv.z);
        XP[3 * 16 + tid] = pack2(xv.w, xv.w);
        XP[4 * 16 + tid] = pack2(act, act);
        XP[5 * 16 + tid] = pack2(st, st);
    }

    // A-fragment base pointers: warp's J tiles are 4w..4w+3
    const uint4* pH = WFhi4 + ((w * 4) * 16) * 32 + lane;
    const uint4* pL = WFlo4 + ((w * 4) * 16) * 32 + lane;

    __syncthreads();

    for (int t = 0; t < NB; t++) {
        // ---- prefetch scalar-tail memory (used ~whole step later) ----
        float pf_tn = 0.f, pf_dn = 0.f;
        float4 pf_x = make_float4(0.f, 0.f, 0.f, 0.f);
        if (tid < MT) {
            pf_tn = TN[(size_t)(base + tid) * NB + t];
            pf_dn = DN[(size_t)(base + tid) * NB + t];
            int tn = (t + 1 < NB) ? t + 1 : NB - 1;
            pf_x = xrow[tn];
        }

        // ======== layer 1: produce h1 hi/lo directly as B-fragments ========
        #pragma unroll 1
        for (int kk = 0; kk < 4; kk++) {
            const int kt = w * 4 + kk;
            const int k0 = kt * 16 + q4 * 2;     // r=0 k-pair
            const int k1 = k0 + 8;               // r=1 k-pair
            ull c0[7], c1[7];
            #pragma unroll
            for (int d = 0; d < 6; d++) {
                c0[d] = *reinterpret_cast<const ull*>(&W1J[d * 256 + k0]);
                c1[d] = *reinterpret_cast<const ull*>(&W1J[d * 256 + k1]);
            }
            c0[6] = *reinterpret_cast<const ull*>(&B1s[k0]);
            c1[6] = *reinterpret_cast<const ull*>(&B1s[k1]);
            #pragma unroll
            for (int mt = 0; mt < 2; mt++) {
                const int m = mt * 8 + g;
                ull x0 = XP[m],      x1 = XP[16 + m], x2 = XP[32 + m];
                ull x3 = XP[48 + m], x4 = XP[64 + m], x5 = XP[80 + m];
                // r = 0
                ull s = c0[6];
                ffma2(s, c0[0], x0); ffma2(s, c0[1], x1); ffma2(s, c0[2], x2);
                ffma2(s, c0[3], x3); ffma2(s, c0[4], x4); ffma2(s, c0[5], x5);
                float s0, s1; unpack2(s, s0, s1);
                s0 = fmaxf(s0, 0.0f); s1 = fmaxf(s1, 0.0f);
                uint32_t hv0 = hi_pair(s0, s1);
                uint32_t lv0 = lo_pair(s0, s1, hv0);
                // r = 1
                s = c1[6];
                ffma2(s, c1[0], x0); ffma2(s, c1[1], x1); ffma2(s, c1[2], x2);
                ffma2(s, c1[3], x3); ffma2(s, c1[4], x4); ffma2(s, c1[5], x5);
                unpack2(s, s0, s1);
                s0 = fmaxf(s0, 0.0f); s1 = fmaxf(s1, 0.0f);
                uint32_t hv1 = hi_pair(s0, s1);
                uint32_t lv1 = lo_pair(s0, s1, hv1);

                const int fi = ((mt * 16 + kt) * 32 + lane) * 2;
                *reinterpret_cast<ull*>(&BFh[fi]) = (ull)hv0 | ((ull)hv1 << 32);
                *reinterpret_cast<ull*>(&BFl[fi]) = (ull)lv0 | ((ull)lv1 << 32);
            }
        }
        __syncthreads();

        // ======== GEMM: 3 bf16 terms, 4 J-tiles x 2 mt-tiles per warp ========
        float d[8][4];   // [jj*2 + mt]
        #pragma unroll
        for (int i = 0; i < 8; i++) { d[i][0] = 0.f; d[i][1] = 0.f; d[i][2] = 0.f; d[i][3] = 0.f; }

        #pragma unroll 1
        for (int kt = 0; kt < 16; kt++) {
            uint4 ah[4], al[4];
            #pragma unroll
            for (int jj = 0; jj < 4; jj++) {
                ah[jj] = pH[(jj * 16 + kt) * 32];
                al[jj] = pL[(jj * 16 + kt) * 32];
            }
            uint32_t bh[2][2];
            #pragma unroll
            for (int mt = 0; mt < 2; mt++) {
                const int fi = ((mt * 16 + kt) * 32 + lane) * 2;
                bh[mt][0] = BFh[fi]; bh[mt][1] = BFh[fi + 1];
            }
            // term 1: Whi * hhi (8 independent MMAs)
            #pragma unroll
            for (int mt = 0; mt < 2; mt++)
                #pragma unroll
                for (int jj = 0; jj < 4; jj++)
                    MMA(d[jj * 2 + mt], ah[jj], bh[mt][0], bh[mt][1]);
            // term 2: Wlo * hhi
            #pragma unroll
            for (int mt = 0; mt < 2; mt++)
                #pragma unroll
                for (int jj = 0; jj < 4; jj++)
                    MMA(d[jj * 2 + mt], al[jj], bh[mt][0], bh[mt][1]);
            // term 3: Whi * hlo
            uint32_t bl[2][2];
            #pragma unroll
            for (int mt = 0; mt < 2; mt++) {
                const int fi = ((mt * 16 + kt) * 32 + lane) * 2;
                bl[mt][0] = BFl[fi]; bl[mt][1] = BFl[fi + 1];
            }
            #pragma unroll
            for (int mt = 0; mt < 2; mt++)
                #pragma unroll
                for (int jj = 0; jj < 4; jj++)
                    MMA(d[jj * 2 + mt], ah[jj], bl[mt][0], bl[mt][1]);
        }

        // ======== epilogue: cm[m] = sum_j w3[j]*relu(D+b2) ========
        float cm[4];
        #pragma unroll
        for (int i = 0; i < 4; i++) cm[i] = 0.0f;
        #pragma unroll
        for (int jj = 0; jj < 4; jj++) {
            #pragma unroll
            for (int mt = 0; mt < 2; mt++) {
                const float* dd = d[jj * 2 + mt];
                cm[2 * mt]     += w3r[jj][0] * fmaxf(dd[0] + b2r[jj][0], 0.0f)
                                + w3r[jj][1] * fmaxf(dd[2] + b2r[jj][1], 0.0f);
                cm[2 * mt + 1] += w3r[jj][0] * fmaxf(dd[1] + b2r[jj][0], 0.0f)
                                + w3r[jj][1] * fmaxf(dd[3] + b2r[jj][1], 0.0f);
            }
        }
        #pragma unroll
        for (int off = 4; off <= 16; off <<= 1) {
            #pragma unroll
            for (int i = 0; i < 4; i++)
                cm[i] += __shfl_xor_sync(0xFFFFFFFFu, cm[i], off);
        }
        if (lane < 4) {
            *reinterpret_cast<float2*>(&RED[w * 16 + lane * 2]) =
                make_float2(cm[0], cm[1]);
            *reinterpret_cast<float2*>(&RED[w * 16 + 8 + lane * 2]) =
                make_float2(cm[2], cm[3]);
        }
        __syncthreads();

        // ======== scalar recurrence (threads 0..15, state in regs) ========
        if (tid < MT) {
            const int m = tid;
            float a_ml = b3v + RED[m] + RED[16 + m] + RED[32 + m] + RED[48 + m];
            a_ml = fmaxf(a_ml, 0.0f);

            float demand = reinterpret_cast<const float*>(XP)[m * 2]; // low word of XP[0][m]
            float a_prior = fminf(__fdiv_rn(fmaxf(st + demand, 0.0f), 0.8f), 10.0f);

            int n = 95 - t;
            float p = (n <= 63) ? __uint_as_float((unsigned)(127 - 2 * n) << 23) : 0.0f;
            float Gamma = 2.0f + 0.5f * (1.0f - p);

            float sgn = (a_ml < a_prior) ? 1.0f : -1.0f;
            float a_out = a_ml +
                fmaxf(fabsf(a_ml - a_prior) - __fdiv_rn(bgt, Gamma), 0.0f) * sgn;

            float ns = fminf(fmaxf(st * (1.0f - pf_dn) + demand
                                   - (0.8f + pf_tn) * a_out, 0.0f), 15.0f);
            float c_cost = 0.1f * ns * ns + ns + 2.0f;

            float ad_new = fabsf(a_out - a_prior);
            float Snew = 0.25f * Sv + ad_new;
            float cum_d = 2.0f * ad_new + 0.375f * Sv;
            float c_prior = fmaxf(2.0f, c_cost - cum_d);
            float cum_c_new = cumc + (1.0f + lam) * c_prior - c_cost;
            float cum_d_g = 0.5f * Snew * (1.0f - p);

            float bgt_if = fmaxf(fmaxf(bgt + per_step - ad_new * Gamma, 0.0f),
                                 cum_c_new - cum_d_g + lam * 2.0f + budH * (float)(t + 2));
            float bgt_else = fmaxf(bgt + per_step - adp * Gamma, 0.0f);

            bool last = (t == NB - 1);
            bgt  = last ? bgt_else : bgt_if;
            cumc = last ? cumc : cum_c_new;
            adp  = ad_new;
            act  = a_out;
            st   = ns;
            Sv   = Snew;
            OUT[(size_t)(base + m) * NB + t] = a_out;

            // stage XP for t+1 from prefetched X
            XP[m]      = pack2(pf_x.x, pf_x.x);
            XP[16 + m] = pack2(pf_x.y, pf_x.y);
            XP[32 + m] = pack2(pf_x.z, pf_x.z);
            XP[48 + m] = pack2(pf_x.w, pf_x.w);
            XP[64 + m] = pack2(act, act);
            XP[80 + m] = pack2(st, st);
        }
        __syncthreads();
    }
}

extern "C" void kernel_launch(void* const* d_in, const int* in_sizes, int n_in,
                              void* d_out, int out_size) {
    (void)in_sizes; (void)n_in; (void)out_size;
    cudaFuncSetAttribute(net_kernel, cudaFuncAttributeMaxDynamicSharedMemorySize, SMEM_TOT);
    prep_kernel<<<256, 128>>>((const float*)d_in[9]);   // W2
    net_kernel<<<NCTA, THREADS, SMEM_TOT>>>(
        (const float*)d_in[0],   // policy_in_c
        (const float*)d_in[1],   // trans_noise
        (const float*)d_in[2],   // demand_noise
        (const float*)d_in[3],   // action_pre
        (const float*)d_in[4],   // state_pre
        (const float*)d_in[5],   // Lambda
        (const float*)d_in[6],   // Budget
        (const float*)d_in[7],   // W1
        (const float*)d_in[8],   // b1
        (const float*)d_in[10],  // b2
        (const float*)d_in[11],  // W3
        (const float*)d_in[12],  // b3
        (float*)d_out);
}

// round 14
// speedup vs baseline: 1.1007x; 1.1007x over previous
#include <cuda_runtime.h>
#include <cstdint>

#define NB      96
#define MT      32
#define THREADS 256
#define NCTA    256

typedef unsigned long long ull;

// W2 fragments, fragment-linear: [J(16)][KT(16)][lane(32)] x uint4(a0..a3)
__device__ uint4 WFhi4[16 * 16 * 32];
__device__ uint4 WFlo4[16 * 16 * 32];

// ---- helpers ----
__device__ __forceinline__ ull pack2(float x, float y) {
    ull r; asm("mov.b64 %0, {%1, %2};" : "=l"(r) : "f"(x), "f"(y)); return r;
}
__device__ __forceinline__ void unpack2(ull v, float& x, float& y) {
    asm("mov.b64 {%0, %1}, %2;" : "=f"(x), "=f"(y) : "l"(v));
}
__device__ __forceinline__ void ffma2(ull& d, ull a, ull b) {
    asm("fma.rn.f32x2 %0, %1, %2, %0;" : "+l"(d) : "l"(a), "l"(b));
}
// low 16 bits = bf16(f0), high 16 = bf16(f1)
__device__ __forceinline__ uint32_t hi_pair(float f0, float f1) {
    uint32_t v; asm("cvt.rn.bf16x2.f32 %0, %1, %2;" : "=r"(v) : "f"(f1), "f"(f0)); return v;
}
__device__ __forceinline__ uint32_t lo_pair(float f0, float f1, uint32_t hp) {
    float h0 = __uint_as_float(hp << 16);
    float h1 = __uint_as_float(hp & 0xFFFF0000u);
    return hi_pair(f0 - h0, f1 - h1);
}

// non-volatile: lets the compiler schedule loads across MMAs
#define MMA(D, A, B0, B1)                                                  \
    asm("mma.sync.aligned.m16n8k16.row.col.f32.bf16.bf16.f32 "             \
        "{%0,%1,%2,%3},{%4,%5,%6,%7},{%8,%9},{%0,%1,%2,%3};"               \
        : "+f"((D)[0]), "+f"((D)[1]), "+f"((D)[2]), "+f"((D)[3])           \
        : "r"((A).x), "r"((A).y), "r"((A).z), "r"((A).w),                  \
          "r"(B0), "r"(B1))

// ---- prepass: W2 fp32 -> bf16 hi/lo fragments ----
__global__ void prep_kernel(const float* __restrict__ W2) {
    int j = blockIdx.x;          // 0..255 (output row)
    int kp = threadIdx.x;        // 0..127 (k-pair)
    int k = 2 * kp;
    float2 f = *reinterpret_cast<const float2*>(W2 + (size_t)j * 256 + k);
    uint32_t hv = hi_pair(f.x, f.y);
    uint32_t lv = lo_pair(f.x, f.y, hv);
    int J = j >> 4, r = j & 15, KT = k >> 4, q = k & 15;
    int a = ((r >> 3) & 1) | ((q >> 3) << 1);
    int lane = ((r & 7) << 2) | ((q & 7) >> 1);
    int idx = ((((J * 16 + KT) * 32 + lane) << 2) | a);
    reinterpret_cast<uint32_t*>(WFhi4)[idx] = hv;
    reinterpret_cast<uint32_t*>(WFlo4)[idx] = lv;
}

// ---- smem layout (bytes) ----
#define OFF_BF   0        // 32768: h1 B-fragments uint4{hh0,hh1,hl0,hl1} [mt4][kt16][lane32]
#define OFF_W1J  32768    // 6144: [c][k] f32, k pair-contiguous
#define OFF_B1   38912    // 1024
#define OFF_XP   39936    // 1536: ull XP[c*32+m] packed broadcast inputs
#define OFF_RED  41472    // 1024: [warp8][m32] f32
#define SMEM_TOT 42496

__global__ __launch_bounds__(THREADS, 2)
void net_kernel(const float* __restrict__ X,      // [8192][96][4]
                const float* __restrict__ TN,     // [8192][96]
                const float* __restrict__ DN,     // [8192][96]
                const float* __restrict__ A0,     // [8192]
                const float* __restrict__ S0,     // [8192]
                const float* __restrict__ LAM,
                const float* __restrict__ BUD,
                const float* __restrict__ W1,     // [256][6]
                const float* __restrict__ B1,     // [256]
                const float* __restrict__ B2,     // [256]
                const float* __restrict__ W3,     // [256]
                const float* __restrict__ B3,     // [1]
                float* __restrict__ OUT)          // [8192][96]
{
    extern __shared__ __align__(16) char smem[];
    uint4*    BF  = reinterpret_cast<uint4*>(smem + OFF_BF);
    float*    W1J = reinterpret_cast<float*>(smem + OFF_W1J);
    float*    B1s = reinterpret_cast<float*>(smem + OFF_B1);
    ull*      XP  = reinterpret_cast<ull*>(smem + OFF_XP);
    float*    RED = reinterpret_cast<float*>(smem + OFF_RED);

    const int tid  = threadIdx.x;
    const int w    = tid >> 5;
    const int lane = tid & 31;
    const int g    = lane >> 2;      // row-group within fragment
    const int q4   = lane & 3;       // col-group within fragment
    const int base = blockIdx.x * MT;

    // stage W1 transposed [c][k] and B1
    for (int i = tid; i < 6 * 256; i += THREADS) {
        int c = i >> 8, k = i & 255;
        W1J[c * 256 + k] = W1[k * 6 + c];
    }
    for (int i = tid; i < 256; i += THREADS) B1s[i] = B1[i];

    const float lam = LAM[0], bud = BUD[0];
    const float budH     = __fdiv_rn(bud, 96.0f);
    const float per_step = lam * 2.0f + budH;
    const float b3v = B3[0];

    // per-thread epilogue constants: j = w*32 + jt*16 + g + 8*h
    float b2r[2][2], w3r[2][2];
    #pragma unroll
    for (int jt = 0; jt < 2; jt++)
        #pragma unroll
        for (int h = 0; h < 2; h++) {
            int j = w * 32 + jt * 16 + g + 8 * h;
            b2r[jt][h] = B2[j];
            w3r[jt][h] = W3[j];
        }

    // register state (threads 0..31) + initial XP staging
    float act = 0.f, st = 0.f, bgt = per_step, cumc = 0.f, adp = 0.f, Sv = 0.f;
    const float4* xrow = reinterpret_cast<const float4*>(X + (size_t)(base + (tid & 31)) * (NB * 4));
    if (tid < MT) {
        act = A0[base + tid];
        st  = S0[base + tid];
        float4 xv = xrow[0];
        XP[0 * 32 + tid] = pack2(xv.x, xv.x);
        XP[1 * 32 + tid] = pack2(xv.y, xv.y);
        XP[2 * 32 + tid] = pack2(xv.z, xv.z);
        XP[3 * 32 + tid] = pack2(xv.w, xv.w);
        XP[4 * 32 + tid] = pack2(act, act);
        XP[5 * 32 + tid] = pack2(st, st);
    }

    // A-fragment pointers: warp's J tiles are 2w and 2w+1
    const uint4* pA0h = WFhi4 + ((2 * w) * 16) * 32 + lane;
    const uint4* pA1h = pA0h + 16 * 32;
    const uint4* pA0l = WFlo4 + ((2 * w) * 16) * 32 + lane;
    const uint4* pA1l = pA0l + 16 * 32;

    __syncthreads();

    for (int t = 0; t < NB; t++) {
        // ---- prefetch scalar-tail memory (consumed after the GEMM) ----
        float pf_tn = 0.f, pf_dn = 0.f;
        float4 pf_x = make_float4(0.f, 0.f, 0.f, 0.f);
        if (tid < MT) {
            pf_tn = TN[(size_t)(base + tid) * NB + t];
            pf_dn = DN[(size_t)(base + tid) * NB + t];
            int tn = (t + 1 < NB) ? t + 1 : NB - 1;
            pf_x = xrow[tn];
        }

        // ======== layer 1: produce h1 hi/lo directly as interleaved B-fragments ========
        #pragma unroll 1
        for (int kk = 0; kk < 2; kk++) {
            const int kt = w * 2 + kk;
            const int k0 = kt * 16 + q4 * 2;     // r=0 k-pair
            const int k1 = k0 + 8;               // r=1 k-pair
            ull c0[7], c1[7];
            #pragma unroll
            for (int d = 0; d < 6; d++) {
                c0[d] = *reinterpret_cast<const ull*>(&W1J[d * 256 + k0]);
                c1[d] = *reinterpret_cast<const ull*>(&W1J[d * 256 + k1]);
            }
            c0[6] = *reinterpret_cast<const ull*>(&B1s[k0]);
            c1[6] = *reinterpret_cast<const ull*>(&B1s[k1]);
            #pragma unroll
            for (int mt = 0; mt < 4; mt++) {
                const int m = mt * 8 + g;
                ull x0 = XP[m],       x1 = XP[32 + m],  x2 = XP[64 + m];
                ull x3 = XP[96 + m],  x4 = XP[128 + m], x5 = XP[160 + m];
                // r = 0
                ull s = c0[6];
                ffma2(s, c0[0], x0); ffma2(s, c0[1], x1); ffma2(s, c0[2], x2);
                ffma2(s, c0[3], x3); ffma2(s, c0[4], x4); ffma2(s, c0[5], x5);
                float s0, s1; unpack2(s, s0, s1);
                s0 = fmaxf(s0, 0.0f); s1 = fmaxf(s1, 0.0f);
                uint32_t hv0 = hi_pair(s0, s1);
                uint32_t lv0 = lo_pair(s0, s1, hv0);
                // r = 1
                s = c1[6];
                ffma2(s, c1[0], x0); ffma2(s, c1[1], x1); ffma2(s, c1[2], x2);
                ffma2(s, c1[3], x3); ffma2(s, c1[4], x4); ffma2(s, c1[5], x5);
                unpack2(s, s0, s1);
                s0 = fmaxf(s0, 0.0f); s1 = fmaxf(s1, 0.0f);
                uint32_t hv1 = hi_pair(s0, s1);
                uint32_t lv1 = lo_pair(s0, s1, hv1);

                BF[(mt * 16 + kt) * 32 + lane] = make_uint4(hv0, hv1, lv0, lv1);
            }
        }
        __syncthreads();

        // ======== GEMM: 3 bf16 terms, accumulator reuse distance = 8 MMAs ========
        float d[8][4];
        #pragma unroll
        for (int i = 0; i < 8; i++) { d[i][0] = 0.f; d[i][1] = 0.f; d[i][2] = 0.f; d[i][3] = 0.f; }

        #pragma unroll 2
        for (int kt = 0; kt < 16; kt++) {
            uint4 ah0 = pA0h[kt * 32];
            uint4 ah1 = pA1h[kt * 32];
            uint4 al0 = pA0l[kt * 32];
            uint4 al1 = pA1l[kt * 32];

            uint4 bf[4];
            #pragma unroll
            for (int mt = 0; mt < 4; mt++)
                bf[mt] = BF[(mt * 16 + kt) * 32 + lane];

            // term 1: Whi * hhi  (8 independent MMAs)
            #pragma unroll
            for (int mt = 0; mt < 4; mt++) {
                MMA(d[mt],     ah0, bf[mt].x, bf[mt].y);
                MMA(d[4 + mt], ah1, bf[mt].x, bf[mt].y);
            }
            // term 2: Wlo * hhi
            #pragma unroll
            for (int mt = 0; mt < 4; mt++) {
                MMA(d[mt],     al0, bf[mt].x, bf[mt].y);
                MMA(d[4 + mt], al1, bf[mt].x, bf[mt].y);
            }
            // term 3: Whi * hlo
            #pragma unroll
            for (int mt = 0; mt < 4; mt++) {
                MMA(d[mt],     ah0, bf[mt].z, bf[mt].w);
                MMA(d[4 + mt], ah1, bf[mt].z, bf[mt].w);
            }
        }

        // ======== epilogue: cm[m] = sum_j w3[j]*relu(D+b2) ========
        float cm[8];
        #pragma unroll
        for (int i = 0; i < 8; i++) cm[i] = 0.0f;
        #pragma unroll
        for (int jt = 0; jt < 2; jt++) {
            #pragma unroll
            for (int mt = 0; mt < 4; mt++) {
                const float* dd = d[jt * 4 + mt];
                cm[2 * mt]     += w3r[jt][0] * fmaxf(dd[0] + b2r[jt][0], 0.0f)
                                + w3r[jt][1] * fmaxf(dd[2] + b2r[jt][1], 0.0f);
                cm[2 * mt + 1] += w3r[jt][0] * fmaxf(dd[1] + b2r[jt][0], 0.0f)
                                + w3r[jt][1] * fmaxf(dd[3] + b2r[jt][1], 0.0f);
            }
        }
        #pragma unroll
        for (int off = 4; off <= 16; off <<= 1) {
            #pragma unroll
            for (int i = 0; i < 8; i++)
                cm[i] += __shfl_xor_sync(0xFFFFFFFFu, cm[i], off);
        }
        if (lane < 4) {
            #pragma unroll
            for (int mt = 0; mt < 4; mt++)
                *reinterpret_cast<float2*>(&RED[w * 32 + mt * 8 + lane * 2]) =
                    make_float2(cm[2 * mt], cm[2 * mt + 1]);
        }
        __syncthreads();

        // ======== scalar recurrence (threads 0..31, state in regs) ========
        if (tid < MT) {
            const int m = tid;
            float a_ml = b3v;
            #pragma unroll
            for (int ww = 0; ww < 8; ww++) a_ml += RED[ww * 32 + m];
            a_ml = fmaxf(a_ml, 0.0f);

            float demand = reinterpret_cast<const float*>(XP)[m * 2]; // low word of XP[0][m]
            float a_prior = fminf(__fdiv_rn(fmaxf(st + demand, 0.0f), 0.8f), 10.0f);

            int n = 95 - t;
            float p = (n <= 63) ? __uint_as_float((unsigned)(127 - 2 * n) << 23) : 0.0f;
            float Gamma = 2.0f + 0.5f * (1.0f - p);

            float sgn = (a_ml < a_prior) ? 1.0f : -1.0f;
            float a_out = a_ml +
                fmaxf(fabsf(a_ml - a_prior) - __fdiv_rn(bgt, Gamma), 0.0f) * sgn;

            float ns = fminf(fmaxf(st * (1.0f - pf_dn) + demand
                                   - (0.8f + pf_tn) * a_out, 0.0f), 15.0f);
            float c_cost = 0.1f * ns * ns + ns + 2.0f;

            float ad_new = fabsf(a_out - a_prior);
            float Snew = 0.25f * Sv + ad_new;
            float cum_d = 2.0f * ad_new + 0.375f * Sv;
            float c_prior = fmaxf(2.0f, c_cost - cum_d);
            float cum_c_new = cumc + (1.0f + lam) * c_prior - c_cost;
            float cum_d_g = 0.5f * Snew * (1.0f - p);

            float bgt_if = fmaxf(fmaxf(bgt + per_step - ad_new * Gamma, 0.0f),
                                 cum_c_new - cum_d_g + lam * 2.0f + budH * (float)(t + 2));
            float bgt_else = fmaxf(bgt + per_step - adp * Gamma, 0.0f);

            bool last = (t == NB - 1);
            bgt  = last ? bgt_else : bgt_if;
            cumc = last ? cumc : cum_c_new;
            adp  = ad_new;
            act  = a_out;
            st   = ns;
            Sv   = Snew;
            OUT[(size_t)(base + m) * NB + t] = a_out;

            // stage XP for t+1 from prefetched X
            XP[m]       = pack2(pf_x.x, pf_x.x);
            XP[32 + m]  = pack2(pf_x.y, pf_x.y);
            XP[64 + m]  = pack2(pf_x.z, pf_x.z);
            XP[96 + m]  = pack2(pf_x.w, pf_x.w);
            XP[128 + m] = pack2(act, act);
            XP[160 + m] = pack2(st, st);
        }
        __syncthreads();
    }
}

extern "C" void kernel_launch(void* const* d_in, const int* in_sizes, int n_in,
                              void* d_out, int out_size) {
    (void)in_sizes; (void)n_in; (void)out_size;
    cudaFuncSetAttribute(net_kernel, cudaFuncAttributeMaxDynamicSharedMemorySize, SMEM_TOT);
    prep_kernel<<<256, 128>>>((const float*)d_in[9]);   // W2
    net_kernel<<<NCTA, THREADS, SMEM_TOT>>>(
        (const float*)d_in[0],   // policy_in_c
        (const float*)d_in[1],   // trans_noise
        (const float*)d_in[2],   // demand_noise
        (const float*)d_in[3],   // action_pre
        (const float*)d_in[4],   // state_pre
        (const float*)d_in[5],   // Lambda
        (const float*)d_in[6],   // Budget
        (const float*)d_in[7],   // W1
        (const float*)d_in[8],   // b1
        (const float*)d_in[10],  // b2
        (const float*)d_in[11],  // W3
        (const float*)d_in[12],  // b3
        (float*)d_out);
}

// round 15
// speedup vs baseline: 1.5025x; 1.3650x over previous
#include <cuda_runtime.h>
#include <cuda_fp16.h>
#include <cstdint>

#define NB      96
#define MT      32
#define THREADS 256
#define NCTA    256

typedef unsigned long long ull;

// W2 fragments (fp16), fragment-linear: [J(16)][KT(16)][lane(32)] x uint4(a0..a3)
__device__ uint4 WFhi4[16 * 16 * 32];
__device__ uint4 WFlo4[16 * 16 * 32];

// ---- helpers ----
__device__ __forceinline__ ull pack2(float x, float y) {
    ull r; asm("mov.b64 %0, {%1, %2};" : "=l"(r) : "f"(x), "f"(y)); return r;
}
__device__ __forceinline__ void unpack2(ull v, float& x, float& y) {
    asm("mov.b64 {%0, %1}, %2;" : "=f"(x), "=f"(y) : "l"(v));
}
__device__ __forceinline__ void ffma2(ull& d, ull a, ull b) {
    asm("fma.rn.f32x2 %0, %1, %2, %0;" : "+l"(d) : "l"(a), "l"(b));
}
// low 16 bits = f16(f0), high 16 = f16(f1)
__device__ __forceinline__ uint32_t f16_pair(float f0, float f1) {
    uint32_t v; asm("cvt.rn.f16x2.f32 %0, %1, %2;" : "=r"(v) : "f"(f1), "f"(f0)); return v;
}

// non-volatile: lets the compiler schedule loads across MMAs
#define MMA(D, A, B0, B1)                                                  \
    asm("mma.sync.aligned.m16n8k16.row.col.f32.f16.f16.f32 "               \
        "{%0,%1,%2,%3},{%4,%5,%6,%7},{%8,%9},{%0,%1,%2,%3};"               \
        : "+f"((D)[0]), "+f"((D)[1]), "+f"((D)[2]), "+f"((D)[3])           \
        : "r"((A).x), "r"((A).y), "r"((A).z), "r"((A).w),                  \
          "r"(B0), "r"(B1))

// ---- prepass: W2 fp32 -> fp16 hi/lo fragments ----
__global__ void prep_kernel(const float* __restrict__ W2) {
    int j = blockIdx.x;          // 0..255 (output row)
    int kp = threadIdx.x;        // 0..127 (k-pair)
    int k = 2 * kp;
    float2 f = *reinterpret_cast<const float2*>(W2 + (size_t)j * 256 + k);
    uint32_t hv = f16_pair(f.x, f.y);
    __half2 hh = *reinterpret_cast<__half2*>(&hv);   // .x = low = f.x
    float l0 = f.x - __half2float(hh.x);
    float l1 = f.y - __half2float(hh.y);
    uint32_t lv = f16_pair(l0, l1);
    int J = j >> 4, r = j & 15, KT = k >> 4, q = k & 15;
    int a = ((r >> 3) & 1) | ((q >> 3) << 1);
    int lane = ((r & 7) << 2) | ((q & 7) >> 1);
    int idx = ((((J * 16 + KT) * 32 + lane) << 2) | a);
    reinterpret_cast<uint32_t*>(WFhi4)[idx] = hv;
    reinterpret_cast<uint32_t*>(WFlo4)[idx] = lv;
}

// ---- smem layout (bytes) ----
#define OFF_BF   0        // 16384: h1 B-fragments uint2{h0,h1} [mt4][kt16][lane32]
#define OFF_W1J  16384    // 6144: [c][k] f32, k pair-contiguous
#define OFF_B1   22528    // 1024
#define OFF_XP   23552    // 1536: ull XP[c*32+m] packed broadcast inputs
#define OFF_RED  25088    // 1024: [warp8][m32] f32
#define SMEM_TOT 26112

__global__ __launch_bounds__(THREADS, 2)
void net_kernel(const float* __restrict__ X,      // [8192][96][4]
                const float* __restrict__ TN,     // [8192][96]
                const float* __restrict__ DN,     // [8192][96]
                const float* __restrict__ A0,     // [8192]
                const float* __restrict__ S0,     // [8192]
                const float* __restrict__ LAM,
                const float* __restrict__ BUD,
                const float* __restrict__ W1,     // [256][6]
                const float* __restrict__ B1,     // [256]
                const float* __restrict__ B2,     // [256]
                const float* __restrict__ W3,     // [256]
                const float* __restrict__ B3,     // [1]
                float* __restrict__ OUT)          // [8192][96]
{
    extern __shared__ __align__(16) char smem[];
    uint2*    BF  = reinterpret_cast<uint2*>(smem + OFF_BF);
    float*    W1J = reinterpret_cast<float*>(smem + OFF_W1J);
    float*    B1s = reinterpret_cast<float*>(smem + OFF_B1);
    ull*      XP  = reinterpret_cast<ull*>(smem + OFF_XP);
    float*    RED = reinterpret_cast<float*>(smem + OFF_RED);

    const int tid  = threadIdx.x;
    const int w    = tid >> 5;
    const int lane = tid & 31;
    const int g    = lane >> 2;      // row-group within fragment
    const int q4   = lane & 3;       // col-group within fragment
    const int base = blockIdx.x * MT;

    // stage W1 transposed [c][k] and B1
    for (int i = tid; i < 6 * 256; i += THREADS) {
        int c = i >> 8, k = i & 255;
        W1J[c * 256 + k] = W1[k * 6 + c];
    }
    for (int i = tid; i < 256; i += THREADS) B1s[i] = B1[i];

    const float lam = LAM[0], bud = BUD[0];
    const float budH     = __fdiv_rn(bud, 96.0f);
    const float per_step = lam * 2.0f + budH;
    const float b3v = B3[0];

    // per-thread epilogue constants: j = w*32 + jt*16 + g + 8*h
    float b2r[2][2], w3r[2][2];
    #pragma unroll
    for (int jt = 0; jt < 2; jt++)
        #pragma unroll
        for (int h = 0; h < 2; h++) {
            int j = w * 32 + jt * 16 + g + 8 * h;
            b2r[jt][h] = B2[j];
            w3r[jt][h] = W3[j];
        }

    // register state (threads 0..31) + initial XP staging
    float act = 0.f, st = 0.f, bgt = per_step, cumc = 0.f, adp = 0.f, Sv = 0.f;
    const float4* xrow = reinterpret_cast<const float4*>(X + (size_t)(base + (tid & 31)) * (NB * 4));
    if (tid < MT) {
        act = A0[base + tid];
        st  = S0[base + tid];
        float4 xv = xrow[0];
        XP[0 * 32 + tid] = pack2(xv.x, xv.x);
        XP[1 * 32 + tid] = pack2(xv.y, xv.y);
        XP[2 * 32 + tid] = pack2(xv.z, xv.z);
        XP[3 * 32 + tid] = pack2(xv.w, xv.w);
        XP[4 * 32 + tid] = pack2(act, act);
        XP[5 * 32 + tid] = pack2(st, st);
    }

    // A-fragment pointers: warp's J tiles are 2w and 2w+1
    const uint4* pA0h = WFhi4 + ((2 * w) * 16) * 32 + lane;
    const uint4* pA1h = pA0h + 16 * 32;
    const uint4* pA0l = WFlo4 + ((2 * w) * 16) * 32 + lane;
    const uint4* pA1l = pA0l + 16 * 32;

    __syncthreads();

    for (int t = 0; t < NB; t++) {
        // ---- prefetch scalar-tail memory (consumed after the GEMM) ----
        float pf_tn = 0.f, pf_dn = 0.f;
        float4 pf_x = make_float4(0.f, 0.f, 0.f, 0.f);
        if (tid < MT) {
            pf_tn = TN[(size_t)(base + tid) * NB + t];
            pf_dn = DN[(size_t)(base + tid) * NB + t];
            int tn = (t + 1 < NB) ? t + 1 : NB - 1;
            pf_x = xrow[tn];
        }

        // ======== layer 1: produce h1 directly as fp16 B-fragments ========
        #pragma unroll 1
        for (int kk = 0; kk < 2; kk++) {
            const int kt = w * 2 + kk;
            const int k0 = kt * 16 + q4 * 2;     // r=0 k-pair
            const int k1 = k0 + 8;               // r=1 k-pair
            ull c0[7], c1[7];
            #pragma unroll
            for (int d = 0; d < 6; d++) {
                c0[d] = *reinterpret_cast<const ull*>(&W1J[d * 256 + k0]);
                c1[d] = *reinterpret_cast<const ull*>(&W1J[d * 256 + k1]);
            }
            c0[6] = *reinterpret_cast<const ull*>(&B1s[k0]);
            c1[6] = *reinterpret_cast<const ull*>(&B1s[k1]);
            #pragma unroll
            for (int mt = 0; mt < 4; mt++) {
                const int m = mt * 8 + g;
                ull x0 = XP[m],       x1 = XP[32 + m],  x2 = XP[64 + m];
                ull x3 = XP[96 + m],  x4 = XP[128 + m], x5 = XP[160 + m];
                // r = 0
                ull s = c0[6];
                ffma2(s, c0[0], x0); ffma2(s, c0[1], x1); ffma2(s, c0[2], x2);
                ffma2(s, c0[3], x3); ffma2(s, c0[4], x4); ffma2(s, c0[5], x5);
                float s0, s1; unpack2(s, s0, s1);
                uint32_t hv0 = f16_pair(fmaxf(s0, 0.0f), fmaxf(s1, 0.0f));
                // r = 1
                s = c1[6];
                ffma2(s, c1[0], x0); ffma2(s, c1[1], x1); ffma2(s, c1[2], x2);
                ffma2(s, c1[3], x3); ffma2(s, c1[4], x4); ffma2(s, c1[5], x5);
                unpack2(s, s0, s1);
                uint32_t hv1 = f16_pair(fmaxf(s0, 0.0f), fmaxf(s1, 0.0f));

                BF[(mt * 16 + kt) * 32 + lane] = make_uint2(hv0, hv1);
            }
        }
        __syncthreads();

        // ======== GEMM: 2 fp16 terms (W 2-level, h 1-level) ========
        float d[8][4];
        #pragma unroll
        for (int i = 0; i < 8; i++) { d[i][0] = 0.f; d[i][1] = 0.f; d[i][2] = 0.f; d[i][3] = 0.f; }

        #pragma unroll 2
        for (int kt = 0; kt < 16; kt++) {
            uint4 ah0 = pA0h[kt * 32];
            uint4 ah1 = pA1h[kt * 32];
            uint4 al0 = pA0l[kt * 32];
            uint4 al1 = pA1l[kt * 32];

            uint2 bf[4];
            #pragma unroll
            for (int mt = 0; mt < 4; mt++)
                bf[mt] = BF[(mt * 16 + kt) * 32 + lane];

            // term 1: Whi * h  (8 independent MMAs)
            #pragma unroll
            for (int mt = 0; mt < 4; mt++) {
                MMA(d[mt],     ah0, bf[mt].x, bf[mt].y);
                MMA(d[4 + mt], ah1, bf[mt].x, bf[mt].y);
            }
            // term 2: Wlo * h
            #pragma unroll
            for (int mt = 0; mt < 4; mt++) {
                MMA(d[mt],     al0, bf[mt].x, bf[mt].y);
                MMA(d[4 + mt], al1, bf[mt].x, bf[mt].y);
            }
        }

        // ======== epilogue: cm[m] = sum_j w3[j]*relu(D+b2) ========
        float cm[8];
        #pragma unroll
        for (int i = 0; i < 8; i++) cm[i] = 0.0f;
        #pragma unroll
        for (int jt = 0; jt < 2; jt++) {
            #pragma unroll
            for (int mt = 0; mt < 4; mt++) {
                const float* dd = d[jt * 4 + mt];
                cm[2 * mt]     += w3r[jt][0] * fmaxf(dd[0] + b2r[jt][0], 0.0f)
                                + w3r[jt][1] * fmaxf(dd[2] + b2r[jt][1], 0.0f);
                cm[2 * mt + 1] += w3r[jt][0] * fmaxf(dd[1] + b2r[jt][0], 0.0f)
                                + w3r[jt][1] * fmaxf(dd[3] + b2r[jt][1], 0.0f);
            }
        }
        #pragma unroll
        for (int off = 4; off <= 16; off <<= 1) {
            #pragma unroll
            for (int i = 0; i < 8; i++)
                cm[i] += __shfl_xor_sync(0xFFFFFFFFu, cm[i], off);
        }
        if (lane < 4) {
            #pragma unroll
            for (int mt = 0; mt < 4; mt++)
                *reinterpret_cast<float2*>(&RED[w * 32 + mt * 8 + lane * 2]) =
                    make_float2(cm[2 * mt], cm[2 * mt + 1]);
        }
        __syncthreads();

        // ======== scalar recurrence (threads 0..31, state in regs) ========
        if (tid < MT) {
            const int m = tid;
            float a_ml = b3v;
            #pragma unroll
            for (int ww = 0; ww < 8; ww++) a_ml += RED[ww * 32 + m];
            a_ml = fmaxf(a_ml, 0.0f);

            float demand = reinterpret_cast<const float*>(XP)[m * 2]; // low word of XP[0][m]
            float a_prior = fminf(__fdiv_rn(fmaxf(st + demand, 0.0f), 0.8f), 10.0f);

            int n = 95 - t;
            float p = (n <= 63) ? __uint_as_float((unsigned)(127 - 2 * n) << 23) : 0.0f;
            float Gamma = 2.0f + 0.5f * (1.0f - p);

            float sgn = (a_ml < a_prior) ? 1.0f : -1.0f;
            float a_out = a_ml +
                fmaxf(fabsf(a_ml - a_prior) - __fdiv_rn(bgt, Gamma), 0.0f) * sgn;

            float ns = fminf(fmaxf(st * (1.0f - pf_dn) + demand
                                   - (0.8f + pf_tn) * a_out, 0.0f), 15.0f);
            float c_cost = 0.1f * ns * ns + ns + 2.0f;

            float ad_new = fabsf(a_out - a_prior);
            float Snew = 0.25f * Sv + ad_new;
            float cum_d = 2.0f * ad_new + 0.375f * Sv;
            float c_prior = fmaxf(2.0f, c_cost - cum_d);
            float cum_c_new = cumc + (1.0f + lam) * c_prior - c_cost;
            float cum_d_g = 0.5f * Snew * (1.0f - p);

            float bgt_if = fmaxf(fmaxf(bgt + per_step - ad_new * Gamma, 0.0f),
                                 cum_c_new - cum_d_g + lam * 2.0f + budH * (float)(t + 2));
            float bgt_else = fmaxf(bgt + per_step - adp * Gamma, 0.0f);

            bool last = (t == NB - 1);
            bgt  = last ? bgt_else : bgt_if;
            cumc = last ? cumc : cum_c_new;
            adp  = ad_new;
            act  = a_out;
            st   = ns;
            Sv   = Snew;
            OUT[(size_t)(base + m) * NB + t] = a_out;

            // stage XP for t+1 from prefetched X
            XP[m]       = pack2(pf_x.x, pf_x.x);
            XP[32 + m]  = pack2(pf_x.y, pf_x.y);
            XP[64 + m]  = pack2(pf_x.z, pf_x.z);
            XP[96 + m]  = pack2(pf_x.w, pf_x.w);
            XP[128 + m] = pack2(act, act);
            XP[160 + m] = pack2(st, st);
        }
        __syncthreads();
    }
}

extern "C" void kernel_launch(void* const* d_in, const int* in_sizes, int n_in,
                              void* d_out, int out_size) {
    (void)in_sizes; (void)n_in; (void)out_size;
    cudaFuncSetAttribute(net_kernel, cudaFuncAttributeMaxDynamicSharedMemorySize, SMEM_TOT);
    prep_kernel<<<256, 128>>>((const float*)d_in[9]);   // W2
    net_kernel<<<NCTA, THREADS, SMEM_TOT>>>(
        (const float*)d_in[0],   // policy_in_c
        (const float*)d_in[1],   // trans_noise
        (const float*)d_in[2],   // demand_noise
        (const float*)d_in[3],   // action_pre
        (const float*)d_in[4],   // state_pre
        (const float*)d_in[5],   // Lambda
        (const float*)d_in[6],   // Budget
        (const float*)d_in[7],   // W1
        (const float*)d_in[8],   // b1
        (const float*)d_in[10],  // b2
        (const float*)d_in[11],  // W3
        (const float*)d_in[12],  // b3
        (float*)d_out);
}

// round 16
// speedup vs baseline: 2.1060x; 1.4017x over previous
#include <cuda_runtime.h>
#include <cuda_fp16.h>
#include <cstdint>

#define NB      96
#define MT      32
#define THREADS 256
#define NCTA    256

typedef unsigned long long ull;

// W2 fragments (fp16, single term): [J(16)][KT(16)][lane(32)] x uint4(a0..a3)
__device__ uint4 WFhi4[16 * 16 * 32];

// ---- helpers ----
__device__ __forceinline__ ull pack2(float x, float y) {
    ull r; asm("mov.b64 %0, {%1, %2};" : "=l"(r) : "f"(x), "f"(y)); return r;
}
__device__ __forceinline__ void unpack2(ull v, float& x, float& y) {
    asm("mov.b64 {%0, %1}, %2;" : "=f"(x), "=f"(y) : "l"(v));
}
__device__ __forceinline__ void ffma2(ull& d, ull a, ull b) {
    asm("fma.rn.f32x2 %0, %1, %2, %0;" : "+l"(d) : "l"(a), "l"(b));
}
// low 16 bits = f16(f0), high 16 = f16(f1)
__device__ __forceinline__ uint32_t f16_pair(float f0, float f1) {
    uint32_t v; asm("cvt.rn.f16x2.f32 %0, %1, %2;" : "=r"(v) : "f"(f1), "f"(f0)); return v;
}

// non-volatile: lets the compiler schedule loads across MMAs
#define MMA(D, A, B0, B1)                                                  \
    asm("mma.sync.aligned.m16n8k16.row.col.f32.f16.f16.f32 "               \
        "{%0,%1,%2,%3},{%4,%5,%6,%7},{%8,%9},{%0,%1,%2,%3};"               \
        : "+f"((D)[0]), "+f"((D)[1]), "+f"((D)[2]), "+f"((D)[3])           \
        : "r"((A).x), "r"((A).y), "r"((A).z), "r"((A).w),                  \
          "r"(B0), "r"(B1))

// ---- prepass: W2 fp32 -> fp16 fragments ----
__global__ void prep_kernel(const float* __restrict__ W2) {
    int j = blockIdx.x;          // 0..255 (output row)
    int kp = threadIdx.x;        // 0..127 (k-pair)
    int k = 2 * kp;
    float2 f = *reinterpret_cast<const float2*>(W2 + (size_t)j * 256 + k);
    uint32_t hv = f16_pair(f.x, f.y);
    int J = j >> 4, r = j & 15, KT = k >> 4, q = k & 15;
    int a = ((r >> 3) & 1) | ((q >> 3) << 1);
    int lane = ((r & 7) << 2) | ((q & 7) >> 1);
    int idx = ((((J * 16 + KT) * 32 + lane) << 2) | a);
    reinterpret_cast<uint32_t*>(WFhi4)[idx] = hv;
}

// ---- smem layout (bytes) ----
#define OFF_BF   0        // 16384: h1 B-fragments uint2{h0,h1} [mt4][kt16][lane32]
#define OFF_W1J  16384    // 6144: [c][k] f32, k pair-contiguous
#define OFF_B1   22528    // 1024
#define OFF_XP   23552    // 1536: ull XP[c*32+m] packed broadcast inputs
#define OFF_RED  25088    // 1024: [warp8][m32] f32
#define SMEM_TOT 26112

__global__ __launch_bounds__(THREADS, 2)
void net_kernel(const float* __restrict__ X,      // [8192][96][4]
                const float* __restrict__ TN,     // [8192][96]
                const float* __restrict__ DN,     // [8192][96]
                const float* __restrict__ A0,     // [8192]
                const float* __restrict__ S0,     // [8192]
                const float* __restrict__ LAM,
                const float* __restrict__ BUD,
                const float* __restrict__ W1,     // [256][6]
                const float* __restrict__ B1,     // [256]
                const float* __restrict__ B2,     // [256]
                const float* __restrict__ W3,     // [256]
                const float* __restrict__ B3,     // [1]
                float* __restrict__ OUT)          // [8192][96]
{
    extern __shared__ __align__(16) char smem[];
    uint2*    BF  = reinterpret_cast<uint2*>(smem + OFF_BF);
    float*    W1J = reinterpret_cast<float*>(smem + OFF_W1J);
    float*    B1s = reinterpret_cast<float*>(smem + OFF_B1);
    ull*      XP  = reinterpret_cast<ull*>(smem + OFF_XP);
    float*    RED = reinterpret_cast<float*>(smem + OFF_RED);

    const int tid  = threadIdx.x;
    const int w    = tid >> 5;
    const int lane = tid & 31;
    const int g    = lane >> 2;      // row-group within fragment
    const int q4   = lane & 3;       // col-group within fragment
    const int base = blockIdx.x * MT;

    // stage W1 transposed [c][k] and B1
    for (int i = tid; i < 6 * 256; i += THREADS) {
        int c = i >> 8, k = i & 255;
        W1J[c * 256 + k] = W1[k * 6 + c];
    }
    for (int i = tid; i < 256; i += THREADS) B1s[i] = B1[i];

    const float lam = LAM[0], bud = BUD[0];
    const float budH     = __fdiv_rn(bud, 96.0f);
    const float per_step = lam * 2.0f + budH;
    const float b3v = B3[0];

    // per-thread epilogue constants: j = w*32 + jt*16 + g + 8*h
    float b2r[2][2], w3r[2][2];
    #pragma unroll
    for (int jt = 0; jt < 2; jt++)
        #pragma unroll
        for (int h = 0; h < 2; h++) {
            int j = w * 32 + jt * 16 + g + 8 * h;
            b2r[jt][h] = B2[j];
            w3r[jt][h] = W3[j];
        }

    // register state (threads 0..31) + initial XP staging
    float act = 0.f, st = 0.f, bgt = per_step, cumc = 0.f, adp = 0.f, Sv = 0.f;
    const float4* xrow = reinterpret_cast<const float4*>(X + (size_t)(base + (tid & 31)) * (NB * 4));
    if (tid < MT) {
        act = A0[base + tid];
        st  = S0[base + tid];
        float4 xv = xrow[0];
        XP[0 * 32 + tid] = pack2(xv.x, xv.x);
        XP[1 * 32 + tid] = pack2(xv.y, xv.y);
        XP[2 * 32 + tid] = pack2(xv.z, xv.z);
        XP[3 * 32 + tid] = pack2(xv.w, xv.w);
        XP[4 * 32 + tid] = pack2(act, act);
        XP[5 * 32 + tid] = pack2(st, st);
    }

    // A-fragment pointers: warp's J tiles are 2w and 2w+1
    const uint4* pA0h = WFhi4 + ((2 * w) * 16) * 32 + lane;
    const uint4* pA1h = pA0h + 16 * 32;

    __syncthreads();

    for (int t = 0; t < NB; t++) {
        // ---- prefetch scalar-tail memory (consumed after the GEMM) ----
        float pf_tn = 0.f, pf_dn = 0.f;
        float4 pf_x = make_float4(0.f, 0.f, 0.f, 0.f);
        if (tid < MT) {
            pf_tn = TN[(size_t)(base + tid) * NB + t];
            pf_dn = DN[(size_t)(base + tid) * NB + t];
            int tn = (t + 1 < NB) ? t + 1 : NB - 1;
            pf_x = xrow[tn];
        }

        // ======== layer 1: produce h1 directly as fp16 B-fragments ========
        #pragma unroll 1
        for (int kk = 0; kk < 2; kk++) {
            const int kt = w * 2 + kk;
            const int k0 = kt * 16 + q4 * 2;     // r=0 k-pair
            const int k1 = k0 + 8;               // r=1 k-pair
            ull c0[7], c1[7];
            #pragma unroll
            for (int d = 0; d < 6; d++) {
                c0[d] = *reinterpret_cast<const ull*>(&W1J[d * 256 + k0]);
                c1[d] = *reinterpret_cast<const ull*>(&W1J[d * 256 + k1]);
            }
            c0[6] = *reinterpret_cast<const ull*>(&B1s[k0]);
            c1[6] = *reinterpret_cast<const ull*>(&B1s[k1]);
            #pragma unroll
            for (int mt = 0; mt < 4; mt++) {
                const int m = mt * 8 + g;
                ull x0 = XP[m],       x1 = XP[32 + m],  x2 = XP[64 + m];
                ull x3 = XP[96 + m],  x4 = XP[128 + m], x5 = XP[160 + m];
                // r = 0
                ull s = c0[6];
                ffma2(s, c0[0], x0); ffma2(s, c0[1], x1); ffma2(s, c0[2], x2);
                ffma2(s, c0[3], x3); ffma2(s, c0[4], x4); ffma2(s, c0[5], x5);
                float s0, s1; unpack2(s, s0, s1);
                uint32_t hv0 = f16_pair(fmaxf(s0, 0.0f), fmaxf(s1, 0.0f));
                // r = 1
                s = c1[6];
                ffma2(s, c1[0], x0); ffma2(s, c1[1], x1); ffma2(s, c1[2], x2);
                ffma2(s, c1[3], x3); ffma2(s, c1[4], x4); ffma2(s, c1[5], x5);
                unpack2(s, s0, s1);
                uint32_t hv1 = f16_pair(fmaxf(s0, 0.0f), fmaxf(s1, 0.0f));

                BF[(mt * 16 + kt) * 32 + lane] = make_uint2(hv0, hv1);
            }
        }
        __syncthreads();

        // ======== GEMM: single fp16 term ========
        float d[8][4];
        #pragma unroll
        for (int i = 0; i < 8; i++) { d[i][0] = 0.f; d[i][1] = 0.f; d[i][2] = 0.f; d[i][3] = 0.f; }

        #pragma unroll 2
        for (int kt = 0; kt < 16; kt++) {
            uint4 ah0 = pA0h[kt * 32];
            uint4 ah1 = pA1h[kt * 32];

            uint2 bf[4];
            #pragma unroll
            for (int mt = 0; mt < 4; mt++)
                bf[mt] = BF[(mt * 16 + kt) * 32 + lane];

            #pragma unroll
            for (int mt = 0; mt < 4; mt++) {
                MMA(d[mt],     ah0, bf[mt].x, bf[mt].y);
                MMA(d[4 + mt], ah1, bf[mt].x, bf[mt].y);
            }
        }

        // ======== epilogue: cm[m] = sum_j w3[j]*relu(D+b2) ========
        float cm[8];
        #pragma unroll
        for (int i = 0; i < 8; i++) cm[i] = 0.0f;
        #pragma unroll
        for (int jt = 0; jt < 2; jt++) {
            #pragma unroll
            for (int mt = 0; mt < 4; mt++) {
                const float* dd = d[jt * 4 + mt];
                cm[2 * mt]     += w3r[jt][0] * fmaxf(dd[0] + b2r[jt][0], 0.0f)
                                + w3r[jt][1] * fmaxf(dd[2] + b2r[jt][1], 0.0f);
                cm[2 * mt + 1] += w3r[jt][0] * fmaxf(dd[1] + b2r[jt][0], 0.0f)
                                + w3r[jt][1] * fmaxf(dd[3] + b2r[jt][1], 0.0f);
            }
        }
        #pragma unroll
        for (int off = 4; off <= 16; off <<= 1) {
            #pragma unroll
            for (int i = 0; i < 8; i++)
                cm[i] += __shfl_xor_sync(0xFFFFFFFFu, cm[i], off);
        }
        if (lane < 4) {
            #pragma unroll
            for (int mt = 0; mt < 4; mt++)
                *reinterpret_cast<float2*>(&RED[w * 32 + mt * 8 + lane * 2]) =
                    make_float2(cm[2 * mt], cm[2 * mt + 1]);
        }
        __syncthreads();

        // ======== scalar recurrence (threads 0..31, state in regs) ========
        if (tid < MT) {
            const int m = tid;
            float a_ml = b3v;
            #pragma unroll
            for (int ww = 0; ww < 8; ww++) a_ml += RED[ww * 32 + m];
            a_ml = fmaxf(a_ml, 0.0f);

            float demand = reinterpret_cast<const float*>(XP)[m * 2]; // low word of XP[0][m]
            float a_prior = fminf(__fdiv_rn(fmaxf(st + demand, 0.0f), 0.8f), 10.0f);

            int n = 95 - t;
            float p = (n <= 63) ? __uint_as_float((unsigned)(127 - 2 * n) << 23) : 0.0f;
            float Gamma = 2.0f + 0.5f * (1.0f - p);

            float sgn = (a_ml < a_prior) ? 1.0f : -1.0f;
            float a_out = a_ml +
                fmaxf(fabsf(a_ml - a_prior) - __fdiv_rn(bgt, Gamma), 0.0f) * sgn;

            float ns = fminf(fmaxf(st * (1.0f - pf_dn) + demand
                                   - (0.8f + pf_tn) * a_out, 0.0f), 15.0f);
            float c_cost = 0.1f * ns * ns + ns + 2.0f;

            float ad_new = fabsf(a_out - a_prior);
            float Snew = 0.25f * Sv + ad_new;
            float cum_d = 2.0f * ad_new + 0.375f * Sv;
            float c_prior = fmaxf(2.0f, c_cost - cum_d);
            float cum_c_new = cumc + (1.0f + lam) * c_prior - c_cost;
            float cum_d_g = 0.5f * Snew * (1.0f - p);

            float bgt_if = fmaxf(fmaxf(bgt + per_step - ad_new * Gamma, 0.0f),
                                 cum_c_new - cum_d_g + lam * 2.0f + budH * (float)(t + 2));
            float bgt_else = fmaxf(bgt + per_step - adp * Gamma, 0.0f);

            bool last = (t == NB - 1);
            bgt  = last ? bgt_else : bgt_if;
            cumc = last ? cumc : cum_c_new;
            adp  = ad_new;
            act  = a_out;
            st   = ns;
            Sv   = Snew;
            OUT[(size_t)(base + m) * NB + t] = a_out;

            // stage XP for t+1 from prefetched X
            XP[m]       = pack2(pf_x.x, pf_x.x);
            XP[32 + m]  = pack2(pf_x.y, pf_x.y);
            XP[64 + m]  = pack2(pf_x.z, pf_x.z);
            XP[96 + m]  = pack2(pf_x.w, pf_x.w);
            XP[128 + m] = pack2(act, act);
            XP[160 + m] = pack2(st, st);
        }
        __syncthreads();
    }
}

extern "C" void kernel_launch(void* const* d_in, const int* in_sizes, int n_in,
                              void* d_out, int out_size) {
    (void)in_sizes; (void)n_in; (void)out_size;
    cudaFuncSetAttribute(net_kernel, cudaFuncAttributeMaxDynamicSharedMemorySize, SMEM_TOT);
    prep_kernel<<<256, 128>>>((const float*)d_in[9]);   // W2
    net_kernel<<<NCTA, THREADS, SMEM_TOT>>>(
        (const float*)d_in[0],   // policy_in_c
        (const float*)d_in[1],   // trans_noise
        (const float*)d_in[2],   // demand_noise
        (const float*)d_in[3],   // action_pre
        (const float*)d_in[4],   // state_pre
        (const float*)d_in[5],   // Lambda
        (const float*)d_in[6],   // Budget
        (const float*)d_in[7],   // W1
        (const float*)d_in[8],   // b1
        (const float*)d_in[10],  // b2
        (const float*)d_in[11],  // W3
        (const float*)d_in[12],  // b3
        (float*)d_out);
}